// round 14
// baseline (speedup 1.0000x reference)
#include <cuda_runtime.h>
#include <cuda_fp16.h>
#include <stdint.h>

// Conv 3x3 s1 p1, NCHW fp32: x[32,128,56,56] * w[256,128,3,3] + bias -> out[32,256,56,56]
// fp16 implicit GEMM on mma.sync.m16n8k16 (fp32 accum).
// R14 = R13 mbarrier ring + fat warp tile: 4 warps x (64x64), 128 thr/CTA, occ 2.

#define N_IMG 32
#define C_IN  128
#define HW    56
#define PIX   3136              // 56*56
#define K_OUT 256
#define NPIX  100352            // 32*3136
#define BM    128               // out-channels per CTA
#define BN    128               // pixels per CTA
#define NKT   18                // K steps: 9 (r,s) x 2 c-halves of 64
#define NTHREADS 128

// ---------------- scratch (device globals; no allocs allowed) ----------------
__device__ __align__(16) __half g_xt[(size_t)NPIX * C_IN];   // NHWC fp16
__device__ __align__(16) __half g_w[NKT * 256 * 64];         // [kt][m][c64] fp16

// ---------------- helpers ----------------
__device__ __forceinline__ uint32_t smem_u32(const void* p) {
    uint32_t a;
    asm("{ .reg .u64 t; cvta.to.shared.u64 t, %1; cvt.u32.u64 %0, t; }" : "=r"(a) : "l"(p));
    return a;
}
__device__ __forceinline__ uint32_t sw128(uint32_t off) { return off ^ ((off >> 3) & 0x70); }

__device__ __forceinline__ void cp16(uint32_t dst, const void* src, int src_sz) {
    asm volatile("cp.async.cg.shared.global [%0], [%1], 16, %2;"
                 :: "r"(dst), "l"(src), "r"(src_sz) : "memory");
}
__device__ __forceinline__ void ldsm4(uint32_t* r, uint32_t a) {
    asm volatile("ldmatrix.sync.aligned.m8n8.x4.shared.b16 {%0,%1,%2,%3}, [%4];"
                 : "=r"(r[0]), "=r"(r[1]), "=r"(r[2]), "=r"(r[3]) : "r"(a));
}
__device__ __forceinline__ void mma_fp16(float* c, const uint32_t* a, const uint32_t* b) {
    asm volatile(
        "mma.sync.aligned.m16n8k16.row.col.f32.f16.f16.f32 "
        "{%0,%1,%2,%3}, {%4,%5,%6,%7}, {%8,%9}, {%0,%1,%2,%3};"
        : "+f"(c[0]), "+f"(c[1]), "+f"(c[2]), "+f"(c[3])
        : "r"(a[0]), "r"(a[1]), "r"(a[2]), "r"(a[3]), "r"(b[0]), "r"(b[1]));
}

// ---------------- mbarrier ops ----------------
#define MBAR_INIT(a, c) asm volatile("mbarrier.init.shared.b64 [%0], %1;" :: "r"(a), "r"(c) : "memory")
#define MBAR_ARRIVE(a)  asm volatile("mbarrier.arrive.shared.b64 _, [%0];" :: "r"(a) : "memory")
#define CP_MBAR_ARRIVE_NOINC(a) \
    asm volatile("cp.async.mbarrier.arrive.noinc.shared.b64 [%0];" :: "r"(a) : "memory")
#define MBAR_WAIT(a, ph) do {                                                        \
    uint32_t _m = (a), _p = (ph), _d;                                                \
    asm volatile("{ .reg .pred p; mbarrier.try_wait.parity.acquire.cta.shared::cta.b64 p, [%1], %2; selp.b32 %0,1,0,p; }" \
                 : "=r"(_d) : "r"(_m), "r"(_p) : "memory");                          \
    if (!_d) {                                                                       \
        asm volatile("{ .reg .pred P1; WL_%=:\n\t"                                   \
                     "mbarrier.try_wait.parity.acquire.cta.shared::cta.b64 P1, [%0], %1, 0x989680;\n\t" \
                     "@P1 bra.uni WD_%=;\n\t bra.uni WL_%=;\n\t WD_%=: }"            \
                     :: "r"(_m), "r"(_p) : "memory");                                \
    }                                                                                \
} while (0)

// ---------------- smem: header + 3-stage ring (A 16K | B 16K) ----------------
#define STAGE_BYTES 32768
#define STAGE_BASE  1024
#define A_OFF(st) (STAGE_BASE + (st) * STAGE_BYTES)
#define B_OFF(st) (STAGE_BASE + (st) * STAGE_BYTES + 16384)
#define SMEM_TOTAL (STAGE_BASE + 3 * STAGE_BYTES)
#define MB_FULL(s)  ((s) * 8)
#define MB_EMPTY(s) (24 + (s) * 8)

// ---------------- prep kernels ----------------
__global__ void noop_kernel() {}   // profiler-alignment pad (4 launches/call)

__global__ void wprep_kernel(const float* __restrict__ w) {
    int i4 = blockIdx.x * 256 + threadIdx.x;   // < 73728
    int m  = i4 / 288;
    int k0 = (i4 - m * 288) * 4;
    float4 v = *reinterpret_cast<const float4*>(w + m * 1152 + k0);
    float f[4] = { v.x, v.y, v.z, v.w };
#pragma unroll
    for (int j = 0; j < 4; ++j) {
        int k  = k0 + j;
        int c  = k / 9;
        int rs = k - c * 9;
        int kt = rs * 2 + (c >> 6);
        g_w[(kt * 256 + m) * 64 + (c & 63)] = __float2half(f[j]);
    }
}

__global__ void xprep_kernel(const float* __restrict__ x) {
    __shared__ float t[32][33];
    const int n  = blockIdx.z;
    const int c0 = blockIdx.y * 32;
    const int p0 = blockIdx.x * 32;
    const int tx = threadIdx.x, ty = threadIdx.y;   // 32 x 8
    const float* src = x + ((size_t)n * C_IN + c0) * PIX + p0;
#pragma unroll
    for (int i = 0; i < 4; ++i) {
        int c = ty + i * 8;
        t[c][tx] = src[(size_t)c * PIX + tx];
    }
    __syncthreads();
    const int tid = ty * 32 + tx;
#pragma unroll
    for (int i = 0; i < 2; ++i) {
        int idx = i * 256 + tid;
        int pr  = idx >> 4;
        int cp  = idx & 15;
        __half2 v = __floats2half2_rn(t[cp * 2][pr], t[cp * 2 + 1][pr]);
        *reinterpret_cast<__half2*>(
            g_xt + ((size_t)n * PIX + p0 + pr) * C_IN + c0 + cp * 2) = v;
    }
}

// ---------------- main conv kernel ----------------
__global__ __launch_bounds__(NTHREADS, 2)
void conv_mma_fp16_kernel(const float* __restrict__ bias, float* __restrict__ out) {
    extern __shared__ char smem[];
    const uint32_t sbase = smem_u32(smem);
    const int tid = threadIdx.x;
    const int wid = tid >> 5;
    const int l   = tid & 31;
    const int pixBase = blockIdx.x * BN;
    const int mBase   = blockIdx.y * BM;
    const int wy = wid & 1;            // M half (64 rows)
    const int wx = wid >> 1;           // N half (64 pixels)

    // mbarriers: full count=128 (per-thread cp arrivals), empty count=4 (per-warp)
    if (tid < 3) {
        MBAR_INIT(sbase + MB_FULL(tid), 128);
        MBAR_INIT(sbase + MB_EMPTY(tid), 4);
    }
    __syncthreads();

    // ---- B-row geometry: each thread owns one pixel row (128B) ----
    const int brow = tid;               // 0..127
    const int p    = pixBase + brow;
    const int bn   = p / PIX;
    const int brem = p - bn * PIX;
    const int bh   = brem / HW;
    const int bw   = brem - bh * HW;
    const size_t bimg = (size_t)bn * PIX;

    auto issue = [&](int kt) {
        const int st = kt % 3;
        // A: 1024 uint4 over 128 threads -> 8 each
        const uint4* wsrc = (const uint4*)g_w + (size_t)(kt * 256 + mBase) * 8;
#pragma unroll
        for (int j = 0; j < 8; ++j) {
            int i = j * 128 + tid;
            uint32_t dst = sbase + A_OFF(st) + sw128((uint32_t)((i >> 3) * 128 + (i & 7) * 16));
            cp16(dst, wsrc + i, 16);
        }
        // B: full 128B row per thread (8 x 16B), zero-fill OOB
        const int rs = kt >> 1, chalf = kt & 1;
        const int r = rs / 3, s = rs - r * 3;
        const int ih = bh + r - 1, iw = bw + s - 1;
        const bool valid = ((unsigned)ih < (unsigned)HW) && ((unsigned)iw < (unsigned)HW);
        const size_t eb = valid ? ((bimg + (size_t)ih * HW + iw) * C_IN + chalf * 64) : 0;
        const int ssz = valid ? 16 : 0;
        const uint4* bsrc = (const uint4*)(g_xt + eb);
#pragma unroll
        for (int j = 0; j < 8; ++j) {
            uint32_t dst = sbase + B_OFF(st) + sw128((uint32_t)(brow * 128 + j * 16));
            cp16(dst, bsrc + j, ssz);
        }
        CP_MBAR_ARRIVE_NOINC(sbase + MB_FULL(st));
    };

    float acc[4][8][4];
#pragma unroll
    for (int i = 0; i < 4; ++i)
#pragma unroll
        for (int j = 0; j < 8; ++j)
#pragma unroll
            for (int q = 0; q < 4; ++q)
                acc[i][j][q] = 0.0f;

    issue(0);
    issue(1);

    const int a_m       = wy * 64 + (l & 15);
    const uint32_t a_kb = (uint32_t)(l >> 4) * 16;
    const int b_n       = wx * 64 + (l & 7) + ((l >> 4) << 3);
    const uint32_t b_kb = (uint32_t)((l >> 3) & 1) * 16;

    for (int kt = 0; kt < NKT; ++kt) {
        const int st = kt % 3;
        MBAR_WAIT(sbase + MB_FULL(st), (uint32_t)((kt / 3) & 1));

        const uint32_t aB = sbase + A_OFF(st);
        const uint32_t bB = sbase + B_OFF(st);

#pragma unroll
        for (int k16 = 0; k16 < 4; ++k16) {
            uint32_t af[4][4], bf[4][4];
            const uint32_t kb = (uint32_t)k16 * 32;
#pragma unroll
            for (int mt = 0; mt < 4; ++mt)
                ldsm4(af[mt], aB + sw128((uint32_t)((a_m + mt * 16) * 128) + kb + a_kb));
#pragma unroll
            for (int np = 0; np < 4; ++np)
                ldsm4(bf[np], bB + sw128((uint32_t)((b_n + np * 16) * 128) + kb + b_kb));
#pragma unroll
            for (int mt = 0; mt < 4; ++mt)
#pragma unroll
                for (int nt = 0; nt < 8; ++nt)
                    mma_fp16(acc[mt][nt], af[mt], &bf[nt >> 1][(nt & 1) * 2]);
        }

        if (l == 0) MBAR_ARRIVE(sbase + MB_EMPTY(st));

        const int ktn = kt + 2;
        if (ktn < NKT) {
            const int st2 = ktn % 3;
            if (ktn >= 3)
                MBAR_WAIT(sbase + MB_EMPTY(st2), (uint32_t)(((ktn / 3) - 1) & 1));
            issue(ktn);
        }
    }

    // epilogue: C frag -> NCHW out (+bias); 8-pixel groups stay in-image (8|3136)
#pragma unroll
    for (int mt = 0; mt < 4; ++mt) {
        const int ch0 = mBase + wy * 64 + mt * 16 + (l >> 2);
        const float bv0 = __ldg(&bias[ch0]);
        const float bv1 = __ldg(&bias[ch0 + 8]);
#pragma unroll
        for (int nt = 0; nt < 8; ++nt) {
            const int p0  = pixBase + wx * 64 + nt * 8 + (l & 3) * 2;
            const int on  = p0 / PIX;
            const int pin = p0 - on * PIX;
            float* o = out + ((size_t)on * K_OUT + ch0) * PIX + pin;
            float2 v0, v1;
            v0.x = acc[mt][nt][0] + bv0; v0.y = acc[mt][nt][1] + bv0;
            v1.x = acc[mt][nt][2] + bv1; v1.y = acc[mt][nt][3] + bv1;
            *(float2*)o             = v0;
            *(float2*)(o + 8 * PIX) = v1;
        }
    }
}

// ---------------- launch ----------------
extern "C" void kernel_launch(void* const* d_in, const int* in_sizes, int n_in,
                              void* d_out, int out_size) {
    const float* x    = (const float*)d_in[0];
    const float* wgt  = (const float*)d_in[1];
    const float* bias = (const float*)d_in[2];
    float* out        = (float*)d_out;

    cudaFuncSetAttribute(conv_mma_fp16_kernel,
                         cudaFuncAttributeMaxDynamicSharedMemorySize, SMEM_TOTAL);

    noop_kernel<<<1, 1>>>();                        // ncu alignment (4 launches/call)
    wprep_kernel<<<73728 / 256, 256>>>(wgt);
    {
        dim3 g(PIX / 32, C_IN / 32, N_IMG);         // (98, 4, 32)
        dim3 b(32, 8);
        xprep_kernel<<<g, b>>>(x);
    }
    conv_mma_fp16_kernel<<<dim3(NPIX / BN, K_OUT / BM), NTHREADS, SMEM_TOTAL>>>(bias, out);
}

// round 15
// speedup vs baseline: 1.0907x; 1.0907x over previous
#include <cuda_runtime.h>
#include <cuda_fp16.h>
#include <stdint.h>

// Conv 3x3 s1 p1, NCHW fp32: x[32,128,56,56] * w[256,128,3,3] + bias -> out[32,256,56,56]
// fp16 implicit GEMM on mma.sync.m16n8k16 (fp32 accum).
// R15 = R13 (champion) + earlier consumer-release (arrive after last ldsm)
//       + relaxed producer empty-wait.

#define N_IMG 32
#define C_IN  128
#define HW    56
#define PIX   3136              // 56*56
#define K_OUT 256
#define NPIX  100352            // 32*3136
#define BM    128               // out-channels per CTA
#define BN    128               // pixels per CTA
#define NKT   18                // K steps: 9 (r,s) x 2 c-halves of 64
#define NTHREADS 256

// ---------------- scratch (device globals; no allocs allowed) ----------------
__device__ __align__(16) __half g_xt[(size_t)NPIX * C_IN];   // NHWC fp16
__device__ __align__(16) __half g_w[NKT * 256 * 64];         // [kt][m][c64] fp16

// ---------------- helpers ----------------
__device__ __forceinline__ uint32_t smem_u32(const void* p) {
    uint32_t a;
    asm("{ .reg .u64 t; cvta.to.shared.u64 t, %1; cvt.u32.u64 %0, t; }" : "=r"(a) : "l"(p));
    return a;
}
__device__ __forceinline__ uint32_t sw128(uint32_t off) { return off ^ ((off >> 3) & 0x70); }

__device__ __forceinline__ void cp16(uint32_t dst, const void* src, int src_sz) {
    asm volatile("cp.async.cg.shared.global [%0], [%1], 16, %2;"
                 :: "r"(dst), "l"(src), "r"(src_sz) : "memory");
}
__device__ __forceinline__ void ldsm4(uint32_t* r, uint32_t a) {
    asm volatile("ldmatrix.sync.aligned.m8n8.x4.shared.b16 {%0,%1,%2,%3}, [%4];"
                 : "=r"(r[0]), "=r"(r[1]), "=r"(r[2]), "=r"(r[3]) : "r"(a));
}
__device__ __forceinline__ void mma_fp16(float* c, const uint32_t* a, const uint32_t* b) {
    asm volatile(
        "mma.sync.aligned.m16n8k16.row.col.f32.f16.f16.f32 "
        "{%0,%1,%2,%3}, {%4,%5,%6,%7}, {%8,%9}, {%0,%1,%2,%3};"
        : "+f"(c[0]), "+f"(c[1]), "+f"(c[2]), "+f"(c[3])
        : "r"(a[0]), "r"(a[1]), "r"(a[2]), "r"(a[3]), "r"(b[0]), "r"(b[1]));
}

// ---------------- mbarrier ops ----------------
#define MBAR_INIT(a, c) asm volatile("mbarrier.init.shared.b64 [%0], %1;" :: "r"(a), "r"(c) : "memory")
#define MBAR_ARRIVE(a)  asm volatile("mbarrier.arrive.shared.b64 _, [%0];" :: "r"(a) : "memory")
#define CP_MBAR_ARRIVE_NOINC(a) \
    asm volatile("cp.async.mbarrier.arrive.noinc.shared.b64 [%0];" :: "r"(a) : "memory")
// acquire wait: consumer side (generic LDS/ldsm follow)
#define MBAR_WAIT(a, ph) do {                                                        \
    uint32_t _m = (a), _p = (ph), _d;                                                \
    asm volatile("{ .reg .pred p; mbarrier.try_wait.parity.acquire.cta.shared::cta.b64 p, [%1], %2; selp.b32 %0,1,0,p; }" \
                 : "=r"(_d) : "r"(_m), "r"(_p) : "memory");                          \
    if (!_d) {                                                                       \
        asm volatile("{ .reg .pred P1; WL_%=:\n\t"                                   \
                     "mbarrier.try_wait.parity.acquire.cta.shared::cta.b64 P1, [%0], %1, 0x989680;\n\t" \
                     "@P1 bra.uni WD_%=;\n\t bra.uni WL_%=;\n\t WD_%=: }"            \
                     :: "r"(_m), "r"(_p) : "memory");                                \
    }                                                                                \
} while (0)
// relaxed wait: producer side only — all post-wait smem writes are cp.async (async proxy)
#define MBAR_WAIT_RELAXED(a, ph) do {                                                \
    uint32_t _m = (a), _p = (ph), _d;                                                \
    asm volatile("{ .reg .pred p; mbarrier.try_wait.parity.relaxed.cta.shared::cta.b64 p, [%1], %2; selp.b32 %0,1,0,p; }" \
                 : "=r"(_d) : "r"(_m), "r"(_p) : "memory");                          \
    if (!_d) {                                                                       \
        asm volatile("{ .reg .pred P1; WL_%=:\n\t"                                   \
                     "mbarrier.try_wait.parity.relaxed.cta.shared::cta.b64 P1, [%0], %1, 0x989680;\n\t" \
                     "@P1 bra.uni WD_%=;\n\t bra.uni WL_%=;\n\t WD_%=: }"            \
                     :: "r"(_m), "r"(_p) : "memory");                                \
    }                                                                                \
} while (0)

// ---------------- smem: header + 3-stage ring (A 16K | B 16K) ----------------
#define STAGE_BYTES 32768
#define STAGE_BASE  1024
#define A_OFF(st) (STAGE_BASE + (st) * STAGE_BYTES)
#define B_OFF(st) (STAGE_BASE + (st) * STAGE_BYTES + 16384)
#define SMEM_TOTAL (STAGE_BASE + 3 * STAGE_BYTES)
#define MB_FULL(s)  ((s) * 8)
#define MB_EMPTY(s) (24 + (s) * 8)

// ---------------- prep kernels ----------------
__global__ void noop_kernel() {}   // profiler-alignment pad (4 launches/call)

__global__ void wprep_kernel(const float* __restrict__ w) {
    int i4 = blockIdx.x * 256 + threadIdx.x;   // < 73728
    int m  = i4 / 288;
    int k0 = (i4 - m * 288) * 4;
    float4 v = *reinterpret_cast<const float4*>(w + m * 1152 + k0);
    float f[4] = { v.x, v.y, v.z, v.w };
#pragma unroll
    for (int j = 0; j < 4; ++j) {
        int k  = k0 + j;
        int c  = k / 9;
        int rs = k - c * 9;
        int kt = rs * 2 + (c >> 6);
        g_w[(kt * 256 + m) * 64 + (c & 63)] = __float2half(f[j]);
    }
}

__global__ void xprep_kernel(const float* __restrict__ x) {
    __shared__ float t[32][33];
    const int n  = blockIdx.z;
    const int c0 = blockIdx.y * 32;
    const int p0 = blockIdx.x * 32;
    const int tx = threadIdx.x, ty = threadIdx.y;   // 32 x 8
    const float* src = x + ((size_t)n * C_IN + c0) * PIX + p0;
#pragma unroll
    for (int i = 0; i < 4; ++i) {
        int c = ty + i * 8;
        t[c][tx] = src[(size_t)c * PIX + tx];
    }
    __syncthreads();
    const int tid = ty * 32 + tx;
#pragma unroll
    for (int i = 0; i < 2; ++i) {
        int idx = i * 256 + tid;
        int pr  = idx >> 4;
        int cp  = idx & 15;
        __half2 v = __floats2half2_rn(t[cp * 2][pr], t[cp * 2 + 1][pr]);
        *reinterpret_cast<__half2*>(
            g_xt + ((size_t)n * PIX + p0 + pr) * C_IN + c0 + cp * 2) = v;
    }
}

// ---------------- main conv kernel ----------------
__global__ __launch_bounds__(NTHREADS, 2)
void conv_mma_fp16_kernel(const float* __restrict__ bias, float* __restrict__ out) {
    extern __shared__ char smem[];
    const uint32_t sbase = smem_u32(smem);
    const int tid = threadIdx.x;
    const int wid = tid >> 5;
    const int l   = tid & 31;
    const int pixBase = blockIdx.x * BN;
    const int mBase   = blockIdx.y * BM;
    const int wy = wid & 1;            // M half (64 rows)
    const int wx = wid >> 1;           // N quarter (32 pixels)

    if (tid < 3) {
        MBAR_INIT(sbase + MB_FULL(tid), 256);
        MBAR_INIT(sbase + MB_EMPTY(tid), 8);
    }
    __syncthreads();

    const int brow = tid >> 1;          // 0..127 (B pixel row)
    const int bhr  = tid & 1;           // half-row (64B)
    const int p    = pixBase + brow;
    const int bn   = p / PIX;
    const int brem = p - bn * PIX;
    const int bh   = brem / HW;
    const int bw   = brem - bh * HW;
    const size_t bimg = (size_t)bn * PIX;

    auto issue = [&](int kt) {
        const int st = kt % 3;
        const uint4* wsrc = (const uint4*)g_w + (size_t)(kt * 256 + mBase) * 8;
#pragma unroll
        for (int j = 0; j < 4; ++j) {
            int i = j * 256 + tid;
            uint32_t dst = sbase + A_OFF(st) + sw128((uint32_t)((i >> 3) * 128 + (i & 7) * 16));
            cp16(dst, wsrc + i, 16);
        }
        const int rs = kt >> 1, chalf = kt & 1;
        const int r = rs / 3, s = rs - r * 3;
        const int ih = bh + r - 1, iw = bw + s - 1;
        const bool valid = ((unsigned)ih < (unsigned)HW) && ((unsigned)iw < (unsigned)HW);
        const size_t eb = valid ? ((bimg + (size_t)ih * HW + iw) * C_IN + chalf * 64 + bhr * 32)
                                : 0;
        const int ssz = valid ? 16 : 0;
        const uint4* bsrc = (const uint4*)(g_xt + eb);
#pragma unroll
        for (int j = 0; j < 4; ++j) {
            uint32_t dst = sbase + B_OFF(st) +
                           sw128((uint32_t)(brow * 128 + bhr * 64 + j * 16));
            cp16(dst, bsrc + j, ssz);
        }
        CP_MBAR_ARRIVE_NOINC(sbase + MB_FULL(st));
    };

    float acc[4][4][4];
#pragma unroll
    for (int i = 0; i < 4; ++i)
#pragma unroll
        for (int j = 0; j < 4; ++j)
#pragma unroll
            for (int q = 0; q < 4; ++q)
                acc[i][j][q] = 0.0f;

    issue(0);
    issue(1);

    const int a_m       = wy * 64 + (l & 15);
    const uint32_t a_kb = (uint32_t)(l >> 4) * 16;
    const int b_n       = wx * 32 + (l & 7) + ((l >> 4) << 3);
    const uint32_t b_kb = (uint32_t)((l >> 3) & 1) * 16;

    for (int kt = 0; kt < NKT; ++kt) {
        const int st = kt % 3;
        MBAR_WAIT(sbase + MB_FULL(st), (uint32_t)((kt / 3) & 1));

        const uint32_t aB = sbase + A_OFF(st);
        const uint32_t bB = sbase + B_OFF(st);

#pragma unroll
        for (int k16 = 0; k16 < 4; ++k16) {
            uint32_t af[4][4], bf[2][4];
            const uint32_t kb = (uint32_t)k16 * 32;
#pragma unroll
            for (int mt = 0; mt < 4; ++mt)
                ldsm4(af[mt], aB + sw128((uint32_t)((a_m + mt * 16) * 128) + kb + a_kb));
#pragma unroll
            for (int np = 0; np < 2; ++np)
                ldsm4(bf[np], bB + sw128((uint32_t)((b_n + np * 16) * 128) + kb + b_kb));

            // consumer-release: after the LAST ldsm of this stage, the warp has
            // finished all smem reads (mbarrier.arrive releases prior loads).
            if (k16 == 3 && l == 0) MBAR_ARRIVE(sbase + MB_EMPTY(st));

#pragma unroll
            for (int mt = 0; mt < 4; ++mt)
#pragma unroll
                for (int nt = 0; nt < 4; ++nt)
                    mma_fp16(acc[mt][nt], af[mt], &bf[nt >> 1][(nt & 1) * 2]);
        }

        const int ktn = kt + 2;
        if (ktn < NKT) {
            const int st2 = ktn % 3;
            if (ktn >= 3)
                MBAR_WAIT_RELAXED(sbase + MB_EMPTY(st2), (uint32_t)(((ktn / 3) - 1) & 1));
            issue(ktn);
        }
    }

    // epilogue: C frag -> NCHW out (+bias); 8-pixel groups stay in-image (8|3136)
#pragma unroll
    for (int mt = 0; mt < 4; ++mt) {
        const int ch0 = mBase + wy * 64 + mt * 16 + (l >> 2);
        const float bv0 = __ldg(&bias[ch0]);
        const float bv1 = __ldg(&bias[ch0 + 8]);
#pragma unroll
        for (int nt = 0; nt < 4; ++nt) {
            const int p0  = pixBase + wx * 32 + nt * 8 + (l & 3) * 2;
            const int on  = p0 / PIX;
            const int pin = p0 - on * PIX;
            float* o = out + ((size_t)on * K_OUT + ch0) * PIX + pin;
            float2 v0, v1;
            v0.x = acc[mt][nt][0] + bv0; v0.y = acc[mt][nt][1] + bv0;
            v1.x = acc[mt][nt][2] + bv1; v1.y = acc[mt][nt][3] + bv1;
            *(float2*)o             = v0;
            *(float2*)(o + 8 * PIX) = v1;
        }
    }
}

// ---------------- launch ----------------
extern "C" void kernel_launch(void* const* d_in, const int* in_sizes, int n_in,
                              void* d_out, int out_size) {
    const float* x    = (const float*)d_in[0];
    const float* wgt  = (const float*)d_in[1];
    const float* bias = (const float*)d_in[2];
    float* out        = (float*)d_out;

    cudaFuncSetAttribute(conv_mma_fp16_kernel,
                         cudaFuncAttributeMaxDynamicSharedMemorySize, SMEM_TOTAL);

    noop_kernel<<<1, 1>>>();                        // ncu alignment (4 launches/call)
    wprep_kernel<<<73728 / 256, 256>>>(wgt);
    {
        dim3 g(PIX / 32, C_IN / 32, N_IMG);         // (98, 4, 32)
        dim3 b(32, 8);
        xprep_kernel<<<g, b>>>(x);
    }
    conv_mma_fp16_kernel<<<dim3(NPIX / BN, K_OUT / BM), NTHREADS, SMEM_TOTAL>>>(bias, out);
}

// round 16
// speedup vs baseline: 1.1185x; 1.0254x over previous
#include <cuda_runtime.h>
#include <cuda_fp16.h>
#include <stdint.h>

// Conv 3x3 s1 p1, NCHW fp32: x[32,128,56,56] * w[256,128,3,3] + bias -> out[32,256,56,56]
// fp16 implicit GEMM on mma.sync.m16n8k16 (fp32 accum).
// R16 = R13 champion main kernel (verbatim) + single fused prep kernel (w + x), no noop.

#define N_IMG 32
#define C_IN  128
#define HW    56
#define PIX   3136              // 56*56
#define K_OUT 256
#define NPIX  100352            // 32*3136
#define BM    128               // out-channels per CTA
#define BN    128               // pixels per CTA
#define NKT   18                // K steps: 9 (r,s) x 2 c-halves of 64
#define NTHREADS 256

// ---------------- scratch (device globals; no allocs allowed) ----------------
__device__ __align__(16) __half g_xt[(size_t)NPIX * C_IN];   // NHWC fp16
__device__ __align__(16) __half g_w[NKT * 256 * 64];         // [kt][m][c64] fp16

// ---------------- helpers ----------------
__device__ __forceinline__ uint32_t smem_u32(const void* p) {
    uint32_t a;
    asm("{ .reg .u64 t; cvta.to.shared.u64 t, %1; cvt.u32.u64 %0, t; }" : "=r"(a) : "l"(p));
    return a;
}
__device__ __forceinline__ uint32_t sw128(uint32_t off) { return off ^ ((off >> 3) & 0x70); }

__device__ __forceinline__ void cp16(uint32_t dst, const void* src, int src_sz) {
    asm volatile("cp.async.cg.shared.global [%0], [%1], 16, %2;"
                 :: "r"(dst), "l"(src), "r"(src_sz) : "memory");
}
__device__ __forceinline__ void ldsm4(uint32_t* r, uint32_t a) {
    asm volatile("ldmatrix.sync.aligned.m8n8.x4.shared.b16 {%0,%1,%2,%3}, [%4];"
                 : "=r"(r[0]), "=r"(r[1]), "=r"(r[2]), "=r"(r[3]) : "r"(a));
}
__device__ __forceinline__ void mma_fp16(float* c, const uint32_t* a, const uint32_t* b) {
    asm volatile(
        "mma.sync.aligned.m16n8k16.row.col.f32.f16.f16.f32 "
        "{%0,%1,%2,%3}, {%4,%5,%6,%7}, {%8,%9}, {%0,%1,%2,%3};"
        : "+f"(c[0]), "+f"(c[1]), "+f"(c[2]), "+f"(c[3])
        : "r"(a[0]), "r"(a[1]), "r"(a[2]), "r"(a[3]), "r"(b[0]), "r"(b[1]));
}

// ---------------- mbarrier ops ----------------
#define MBAR_INIT(a, c) asm volatile("mbarrier.init.shared.b64 [%0], %1;" :: "r"(a), "r"(c) : "memory")
#define MBAR_ARRIVE(a)  asm volatile("mbarrier.arrive.shared.b64 _, [%0];" :: "r"(a) : "memory")
#define CP_MBAR_ARRIVE_NOINC(a) \
    asm volatile("cp.async.mbarrier.arrive.noinc.shared.b64 [%0];" :: "r"(a) : "memory")
#define MBAR_WAIT(a, ph) do {                                                        \
    uint32_t _m = (a), _p = (ph), _d;                                                \
    asm volatile("{ .reg .pred p; mbarrier.try_wait.parity.acquire.cta.shared::cta.b64 p, [%1], %2; selp.b32 %0,1,0,p; }" \
                 : "=r"(_d) : "r"(_m), "r"(_p) : "memory");                          \
    if (!_d) {                                                                       \
        asm volatile("{ .reg .pred P1; WL_%=:\n\t"                                   \
                     "mbarrier.try_wait.parity.acquire.cta.shared::cta.b64 P1, [%0], %1, 0x989680;\n\t" \
                     "@P1 bra.uni WD_%=;\n\t bra.uni WL_%=;\n\t WD_%=: }"            \
                     :: "r"(_m), "r"(_p) : "memory");                                \
    }                                                                                \
} while (0)

// ---------------- smem: header + 3-stage ring (A 16K | B 16K) ----------------
#define STAGE_BYTES 32768
#define STAGE_BASE  1024
#define A_OFF(st) (STAGE_BASE + (st) * STAGE_BYTES)
#define B_OFF(st) (STAGE_BASE + (st) * STAGE_BYTES + 16384)
#define SMEM_TOTAL (STAGE_BASE + 3 * STAGE_BYTES)
#define MB_FULL(s)  ((s) * 8)
#define MB_EMPTY(s) (24 + (s) * 8)

// ---------------- fused prep kernel ----------------
// blocks [0, 288): weight transform (float4 reads, 4 elems/thread)
// blocks [288, 288+12544): x NCHW fp32 -> NHWC fp16 (32ch x 32pix transpose tiles)
#define WPREP_BLOCKS 288
#define XPREP_BLOCKS (98 * 4 * 32)   // 12544

__global__ void prep_kernel(const float* __restrict__ w, const float* __restrict__ x) {
    if (blockIdx.x < WPREP_BLOCKS) {
        int i4 = blockIdx.x * 256 + threadIdx.x;   // < 73728
        int m  = i4 / 288;
        int k0 = (i4 - m * 288) * 4;
        float4 v = *reinterpret_cast<const float4*>(w + m * 1152 + k0);
        float f[4] = { v.x, v.y, v.z, v.w };
#pragma unroll
        for (int j = 0; j < 4; ++j) {
            int k  = k0 + j;
            int c  = k / 9;
            int rs = k - c * 9;
            int kt = rs * 2 + (c >> 6);
            g_w[(kt * 256 + m) * 64 + (c & 63)] = __float2half(f[j]);
        }
        return;
    }
    // ---- x transform ----
    __shared__ float t[32][33];
    const int bx = blockIdx.x - WPREP_BLOCKS;      // < 12544
    const int pb = bx % 98;
    const int cb = (bx / 98) & 3;
    const int n  = bx / 392;
    const int c0 = cb * 32;
    const int p0 = pb * 32;
    const int tid = threadIdx.x;
    const int tx = tid & 31, ty = tid >> 5;        // 32 x 8
    const float* src = x + ((size_t)n * C_IN + c0) * PIX + p0;
#pragma unroll
    for (int i = 0; i < 4; ++i) {
        int c = ty + i * 8;
        t[c][tx] = src[(size_t)c * PIX + tx];
    }
    __syncthreads();
#pragma unroll
    for (int i = 0; i < 2; ++i) {
        int idx = i * 256 + tid;      // 0..511 = 32 pixels x 16 ch-pairs
        int pr  = idx >> 4;
        int cp  = idx & 15;
        __half2 v = __floats2half2_rn(t[cp * 2][pr], t[cp * 2 + 1][pr]);
        *reinterpret_cast<__half2*>(
            g_xt + ((size_t)n * PIX + p0 + pr) * C_IN + c0 + cp * 2) = v;
    }
}

// ---------------- main conv kernel (R13 verbatim) ----------------
__global__ __launch_bounds__(NTHREADS, 2)
void conv_mma_fp16_kernel(const float* __restrict__ bias, float* __restrict__ out) {
    extern __shared__ char smem[];
    const uint32_t sbase = smem_u32(smem);
    const int tid = threadIdx.x;
    const int wid = tid >> 5;
    const int l   = tid & 31;
    const int pixBase = blockIdx.x * BN;
    const int mBase   = blockIdx.y * BM;
    const int wy = wid & 1;            // M half (64 rows)
    const int wx = wid >> 1;           // N quarter (32 pixels)

    if (tid < 3) {
        MBAR_INIT(sbase + MB_FULL(tid), 256);
        MBAR_INIT(sbase + MB_EMPTY(tid), 8);
    }
    __syncthreads();

    const int brow = tid >> 1;          // 0..127 (B pixel row)
    const int bhr  = tid & 1;           // half-row (64B)
    const int p    = pixBase + brow;
    const int bn   = p / PIX;
    const int brem = p - bn * PIX;
    const int bh   = brem / HW;
    const int bw   = brem - bh * HW;
    const size_t bimg = (size_t)bn * PIX;

    auto issue = [&](int kt) {
        const int st = kt % 3;
        const uint4* wsrc = (const uint4*)g_w + (size_t)(kt * 256 + mBase) * 8;
#pragma unroll
        for (int j = 0; j < 4; ++j) {
            int i = j * 256 + tid;
            uint32_t dst = sbase + A_OFF(st) + sw128((uint32_t)((i >> 3) * 128 + (i & 7) * 16));
            cp16(dst, wsrc + i, 16);
        }
        const int rs = kt >> 1, chalf = kt & 1;
        const int r = rs / 3, s = rs - r * 3;
        const int ih = bh + r - 1, iw = bw + s - 1;
        const bool valid = ((unsigned)ih < (unsigned)HW) && ((unsigned)iw < (unsigned)HW);
        const size_t eb = valid ? ((bimg + (size_t)ih * HW + iw) * C_IN + chalf * 64 + bhr * 32)
                                : 0;
        const int ssz = valid ? 16 : 0;
        const uint4* bsrc = (const uint4*)(g_xt + eb);
#pragma unroll
        for (int j = 0; j < 4; ++j) {
            uint32_t dst = sbase + B_OFF(st) +
                           sw128((uint32_t)(brow * 128 + bhr * 64 + j * 16));
            cp16(dst, bsrc + j, ssz);
        }
        CP_MBAR_ARRIVE_NOINC(sbase + MB_FULL(st));
    };

    float acc[4][4][4];
#pragma unroll
    for (int i = 0; i < 4; ++i)
#pragma unroll
        for (int j = 0; j < 4; ++j)
#pragma unroll
            for (int q = 0; q < 4; ++q)
                acc[i][j][q] = 0.0f;

    issue(0);
    issue(1);

    const int a_m       = wy * 64 + (l & 15);
    const uint32_t a_kb = (uint32_t)(l >> 4) * 16;
    const int b_n       = wx * 32 + (l & 7) + ((l >> 4) << 3);
    const uint32_t b_kb = (uint32_t)((l >> 3) & 1) * 16;

    for (int kt = 0; kt < NKT; ++kt) {
        const int st = kt % 3;
        MBAR_WAIT(sbase + MB_FULL(st), (uint32_t)((kt / 3) & 1));

        const uint32_t aB = sbase + A_OFF(st);
        const uint32_t bB = sbase + B_OFF(st);

#pragma unroll
        for (int k16 = 0; k16 < 4; ++k16) {
            uint32_t af[4][4], bf[2][4];
            const uint32_t kb = (uint32_t)k16 * 32;
#pragma unroll
            for (int mt = 0; mt < 4; ++mt)
                ldsm4(af[mt], aB + sw128((uint32_t)((a_m + mt * 16) * 128) + kb + a_kb));
#pragma unroll
            for (int np = 0; np < 2; ++np)
                ldsm4(bf[np], bB + sw128((uint32_t)((b_n + np * 16) * 128) + kb + b_kb));
#pragma unroll
            for (int mt = 0; mt < 4; ++mt)
#pragma unroll
                for (int nt = 0; nt < 4; ++nt)
                    mma_fp16(acc[mt][nt], af[mt], &bf[nt >> 1][(nt & 1) * 2]);
        }

        if (l == 0) MBAR_ARRIVE(sbase + MB_EMPTY(st));

        const int ktn = kt + 2;
        if (ktn < NKT) {
            const int st2 = ktn % 3;
            if (ktn >= 3)
                MBAR_WAIT(sbase + MB_EMPTY(st2), (uint32_t)(((ktn / 3) - 1) & 1));
            issue(ktn);
        }
    }

    // epilogue: C frag -> NCHW out (+bias); 8-pixel groups stay in-image (8|3136)
#pragma unroll
    for (int mt = 0; mt < 4; ++mt) {
        const int ch0 = mBase + wy * 64 + mt * 16 + (l >> 2);
        const float bv0 = __ldg(&bias[ch0]);
        const float bv1 = __ldg(&bias[ch0 + 8]);
#pragma unroll
        for (int nt = 0; nt < 4; ++nt) {
            const int p0  = pixBase + wx * 32 + nt * 8 + (l & 3) * 2;
            const int on  = p0 / PIX;
            const int pin = p0 - on * PIX;
            float* o = out + ((size_t)on * K_OUT + ch0) * PIX + pin;
            float2 v0, v1;
            v0.x = acc[mt][nt][0] + bv0; v0.y = acc[mt][nt][1] + bv0;
            v1.x = acc[mt][nt][2] + bv1; v1.y = acc[mt][nt][3] + bv1;
            *(float2*)o             = v0;
            *(float2*)(o + 8 * PIX) = v1;
        }
    }
}

// ---------------- launch ----------------
extern "C" void kernel_launch(void* const* d_in, const int* in_sizes, int n_in,
                              void* d_out, int out_size) {
    const float* x    = (const float*)d_in[0];
    const float* wgt  = (const float*)d_in[1];
    const float* bias = (const float*)d_in[2];
    float* out        = (float*)d_out;

    cudaFuncSetAttribute(conv_mma_fp16_kernel,
                         cudaFuncAttributeMaxDynamicSharedMemorySize, SMEM_TOTAL);

    prep_kernel<<<WPREP_BLOCKS + XPREP_BLOCKS, 256>>>(wgt, x);   // fused w + x transform
    conv_mma_fp16_kernel<<<dim3(NPIX / BN, K_OUT / BM), NTHREADS, SMEM_TOTAL>>>(bias, out);
}

// round 17
// speedup vs baseline: 1.1426x; 1.0215x over previous
#include <cuda_runtime.h>
#include <cuda_fp16.h>
#include <stdint.h>

// Conv 3x3 s1 p1, NCHW fp32: x[32,128,56,56] * w[256,128,3,3] + bias -> out[32,256,56,56]
// fp16 implicit GEMM on mma.sync.m16n8k16 (fp32 accum).
// R17 = R16 prep + PERSISTENT main kernel: 304 CTAs, static tile schedule,
//       continuous mbarrier ring across tiles (no drain/refill between tiles).

#define N_IMG 32
#define C_IN  128
#define HW    56
#define PIX   3136              // 56*56
#define K_OUT 256
#define NPIX  100352            // 32*3136
#define BM    128               // out-channels per tile
#define BN    128               // pixels per tile
#define NKT   18                // K steps per tile
#define NTHREADS 256
#define NCTAS  304              // 2 per SM x 152 SMs
#define NTILES 1568             // (NPIX/BN) * (K_OUT/BM)
#define PIXT_STRIDE 152         // pixTile advance per owned tile (NCTAS/2)

// ---------------- scratch (device globals; no allocs allowed) ----------------
__device__ __align__(16) __half g_xt[(size_t)NPIX * C_IN];   // NHWC fp16
__device__ __align__(16) __half g_w[NKT * 256 * 64];         // [kt][m][c64] fp16

// ---------------- helpers ----------------
__device__ __forceinline__ uint32_t smem_u32(const void* p) {
    uint32_t a;
    asm("{ .reg .u64 t; cvta.to.shared.u64 t, %1; cvt.u32.u64 %0, t; }" : "=r"(a) : "l"(p));
    return a;
}
__device__ __forceinline__ uint32_t sw128(uint32_t off) { return off ^ ((off >> 3) & 0x70); }

__device__ __forceinline__ void cp16(uint32_t dst, const void* src, int src_sz) {
    asm volatile("cp.async.cg.shared.global [%0], [%1], 16, %2;"
                 :: "r"(dst), "l"(src), "r"(src_sz) : "memory");
}
__device__ __forceinline__ void ldsm4(uint32_t* r, uint32_t a) {
    asm volatile("ldmatrix.sync.aligned.m8n8.x4.shared.b16 {%0,%1,%2,%3}, [%4];"
                 : "=r"(r[0]), "=r"(r[1]), "=r"(r[2]), "=r"(r[3]) : "r"(a));
}
__device__ __forceinline__ void mma_fp16(float* c, const uint32_t* a, const uint32_t* b) {
    asm volatile(
        "mma.sync.aligned.m16n8k16.row.col.f32.f16.f16.f32 "
        "{%0,%1,%2,%3}, {%4,%5,%6,%7}, {%8,%9}, {%0,%1,%2,%3};"
        : "+f"(c[0]), "+f"(c[1]), "+f"(c[2]), "+f"(c[3])
        : "r"(a[0]), "r"(a[1]), "r"(a[2]), "r"(a[3]), "r"(b[0]), "r"(b[1]));
}

// ---------------- mbarrier ops ----------------
#define MBAR_INIT(a, c) asm volatile("mbarrier.init.shared.b64 [%0], %1;" :: "r"(a), "r"(c) : "memory")
#define MBAR_ARRIVE(a)  asm volatile("mbarrier.arrive.shared.b64 _, [%0];" :: "r"(a) : "memory")
#define CP_MBAR_ARRIVE_NOINC(a) \
    asm volatile("cp.async.mbarrier.arrive.noinc.shared.b64 [%0];" :: "r"(a) : "memory")
#define MBAR_WAIT(a, ph) do {                                                        \
    uint32_t _m = (a), _p = (ph), _d;                                                \
    asm volatile("{ .reg .pred p; mbarrier.try_wait.parity.acquire.cta.shared::cta.b64 p, [%1], %2; selp.b32 %0,1,0,p; }" \
                 : "=r"(_d) : "r"(_m), "r"(_p) : "memory");                          \
    if (!_d) {                                                                       \
        asm volatile("{ .reg .pred P1; WL_%=:\n\t"                                   \
                     "mbarrier.try_wait.parity.acquire.cta.shared::cta.b64 P1, [%0], %1, 0x989680;\n\t" \
                     "@P1 bra.uni WD_%=;\n\t bra.uni WL_%=;\n\t WD_%=: }"            \
                     :: "r"(_m), "r"(_p) : "memory");                                \
    }                                                                                \
} while (0)

// ---------------- smem: header + 3-stage ring (A 16K | B 16K) ----------------
#define STAGE_BYTES 32768
#define STAGE_BASE  1024
#define A_OFF(st) (STAGE_BASE + (st) * STAGE_BYTES)
#define B_OFF(st) (STAGE_BASE + (st) * STAGE_BYTES + 16384)
#define SMEM_TOTAL (STAGE_BASE + 3 * STAGE_BYTES)
#define MB_FULL(s)  ((s) * 8)
#define MB_EMPTY(s) (24 + (s) * 8)

// ---------------- fused prep kernel (R16, unchanged) ----------------
#define WPREP_BLOCKS 288
#define XPREP_BLOCKS (98 * 4 * 32)   // 12544

__global__ void prep_kernel(const float* __restrict__ w, const float* __restrict__ x) {
    if (blockIdx.x < WPREP_BLOCKS) {
        int i4 = blockIdx.x * 256 + threadIdx.x;
        int m  = i4 / 288;
        int k0 = (i4 - m * 288) * 4;
        float4 v = *reinterpret_cast<const float4*>(w + m * 1152 + k0);
        float f[4] = { v.x, v.y, v.z, v.w };
#pragma unroll
        for (int j = 0; j < 4; ++j) {
            int k  = k0 + j;
            int c  = k / 9;
            int rs = k - c * 9;
            int kt = rs * 2 + (c >> 6);
            g_w[(kt * 256 + m) * 64 + (c & 63)] = __float2half(f[j]);
        }
        return;
    }
    __shared__ float t[32][33];
    const int bx = blockIdx.x - WPREP_BLOCKS;
    const int pb = bx % 98;
    const int cb = (bx / 98) & 3;
    const int n  = bx / 392;
    const int c0 = cb * 32;
    const int p0 = pb * 32;
    const int tid = threadIdx.x;
    const int tx = tid & 31, ty = tid >> 5;
    const float* src = x + ((size_t)n * C_IN + c0) * PIX + p0;
#pragma unroll
    for (int i = 0; i < 4; ++i) {
        int c = ty + i * 8;
        t[c][tx] = src[(size_t)c * PIX + tx];
    }
    __syncthreads();
#pragma unroll
    for (int i = 0; i < 2; ++i) {
        int idx = i * 256 + tid;
        int pr  = idx >> 4;
        int cp  = idx & 15;
        __half2 v = __floats2half2_rn(t[cp * 2][pr], t[cp * 2 + 1][pr]);
        *reinterpret_cast<__half2*>(
            g_xt + ((size_t)n * PIX + p0 + pr) * C_IN + c0 + cp * 2) = v;
    }
}

// ---------------- main conv kernel: persistent, continuous ring ----------------
__global__ __launch_bounds__(NTHREADS, 2)
void conv_mma_fp16_kernel(const float* __restrict__ bias, float* __restrict__ out) {
    extern __shared__ char smem[];
    const uint32_t sbase = smem_u32(smem);
    const int tid = threadIdx.x;
    const int wid = tid >> 5;
    const int l   = tid & 31;
    const int bid = blockIdx.x;

    if (tid < 3) {
        MBAR_INIT(sbase + MB_FULL(tid), 256);
        MBAR_INIT(sbase + MB_EMPTY(tid), 8);
    }
    __syncthreads();

    const int myTiles  = (NTILES - 1 - bid) / NCTAS + 1;      // 6 for bid<48, else 5
    const int mBase    = (bid & 1) * BM;                       // constant per CTA
    const int pixTile0 = bid >> 1;                             // +152 per owned tile

    const int wy = wid & 1;            // M half (64 rows)
    const int wx = wid >> 1;           // N quarter (32 pixels)
    const int brow = tid >> 1;          // B pixel row 0..127
    const int bhr  = tid & 1;           // half-row (64B)

    // ---- producer state (geometry for the tile currently being loaded) ----
    int    pbh, pbw;
    size_t pbimg;
    auto setGeo = [&](int pixTile) {
        const int p    = pixTile * BN + brow;
        const int bn   = p / PIX;
        const int brem = p - bn * PIX;
        pbh   = brem / HW;
        pbw   = brem - pbh * HW;
        pbimg = (size_t)bn * PIX;
    };
    int ppixTile = pixTile0;
    int pkt = 0;                        // producer kt within its tile
    setGeo(ppixTile);

    auto issue = [&]() {
        const int st = pkt % 3;
        const uint4* wsrc = (const uint4*)g_w + (size_t)(pkt * 256 + mBase) * 8;
#pragma unroll
        for (int j = 0; j < 4; ++j) {
            int i = j * 256 + tid;
            uint32_t dst = sbase + A_OFF(st) + sw128((uint32_t)((i >> 3) * 128 + (i & 7) * 16));
            cp16(dst, wsrc + i, 16);
        }
        const int rs = pkt >> 1, chalf = pkt & 1;
        const int r = rs / 3, s = rs - r * 3;
        const int ih = pbh + r - 1, iw = pbw + s - 1;
        const bool valid = ((unsigned)ih < (unsigned)HW) && ((unsigned)iw < (unsigned)HW);
        const size_t eb = valid ? ((pbimg + (size_t)ih * HW + iw) * C_IN + chalf * 64 + bhr * 32)
                                : 0;
        const int ssz = valid ? 16 : 0;
        const uint4* bsrc = (const uint4*)(g_xt + eb);
#pragma unroll
        for (int j = 0; j < 4; ++j) {
            uint32_t dst = sbase + B_OFF(st) +
                           sw128((uint32_t)(brow * 128 + bhr * 64 + j * 16));
            cp16(dst, bsrc + j, ssz);
        }
        CP_MBAR_ARRIVE_NOINC(sbase + MB_FULL(st));
        // advance producer step (arithmetic only; safe past last tile — never deref'd)
        if (++pkt == NKT) { pkt = 0; ppixTile += PIXT_STRIDE; setGeo(ppixTile); }
    };

    float acc[4][4][4];
#pragma unroll
    for (int i = 0; i < 4; ++i)
#pragma unroll
        for (int j = 0; j < 4; ++j)
#pragma unroll
            for (int q = 0; q < 4; ++q)
                acc[i][j][q] = 0.0f;

    issue();    // global step 0
    issue();    // global step 1

    const int a_m       = wy * 64 + (l & 15);
    const uint32_t a_kb = (uint32_t)(l >> 4) * 16;
    const int b_n       = wx * 32 + (l & 7) + ((l >> 4) << 3);
    const uint32_t b_kb = (uint32_t)((l >> 3) & 1) * 16;

    for (int ti = 0; ti < myTiles; ++ti) {
        const int pixBase = (pixTile0 + ti * PIXT_STRIDE) * BN;

        for (int kt = 0; kt < NKT; ++kt) {
            const int st = kt % 3;
            MBAR_WAIT(sbase + MB_FULL(st), (uint32_t)((kt / 3) & 1));

            const uint32_t aB = sbase + A_OFF(st);
            const uint32_t bB = sbase + B_OFF(st);

#pragma unroll
            for (int k16 = 0; k16 < 4; ++k16) {
                uint32_t af[4][4], bf[2][4];
                const uint32_t kb = (uint32_t)k16 * 32;
#pragma unroll
                for (int mt = 0; mt < 4; ++mt)
                    ldsm4(af[mt], aB + sw128((uint32_t)((a_m + mt * 16) * 128) + kb + a_kb));
#pragma unroll
                for (int np = 0; np < 2; ++np)
                    ldsm4(bf[np], bB + sw128((uint32_t)((b_n + np * 16) * 128) + kb + b_kb));
#pragma unroll
                for (int mt = 0; mt < 4; ++mt)
#pragma unroll
                    for (int nt = 0; nt < 4; ++nt)
                        mma_fp16(acc[mt][nt], af[mt], &bf[nt >> 1][(nt & 1) * 2]);
            }

            if (l == 0) MBAR_ARRIVE(sbase + MB_EMPTY(st));

            // issue global step gstep+2 (crosses into next tile at kt=16,17)
            const bool more = !(ti == myTiles - 1 && kt >= NKT - 2);
            if (more) {
                if (ti > 0 || kt >= 1) {
                    // stage of step gstep+2 == producer's current stage (pkt%3)
                    MBAR_WAIT(sbase + MB_EMPTY(pkt % 3),
                              (uint32_t)((((kt + 2) / 3) - 1) & 1));
                }
                issue();
            }
        }

        // ---- per-tile epilogue (overlaps with next tile's in-flight loads) ----
#pragma unroll
        for (int mt = 0; mt < 4; ++mt) {
            const int ch0 = mBase + wy * 64 + mt * 16 + (l >> 2);
            const float bv0 = __ldg(&bias[ch0]);
            const float bv1 = __ldg(&bias[ch0 + 8]);
#pragma unroll
            for (int nt = 0; nt < 4; ++nt) {
                const int p0  = pixBase + wx * 32 + nt * 8 + (l & 3) * 2;
                const int on  = p0 / PIX;
                const int pin = p0 - on * PIX;
                float* o = out + ((size_t)on * K_OUT + ch0) * PIX + pin;
                float2 v0, v1;
                v0.x = acc[mt][nt][0] + bv0; v0.y = acc[mt][nt][1] + bv0;
                v1.x = acc[mt][nt][2] + bv1; v1.y = acc[mt][nt][3] + bv1;
                *(float2*)o             = v0;
                *(float2*)(o + 8 * PIX) = v1;
            }
        }
        // reset accumulators for next tile
#pragma unroll
        for (int i = 0; i < 4; ++i)
#pragma unroll
            for (int j = 0; j < 4; ++j)
#pragma unroll
                for (int q = 0; q < 4; ++q)
                    acc[i][j][q] = 0.0f;
    }
}

// ---------------- launch ----------------
extern "C" void kernel_launch(void* const* d_in, const int* in_sizes, int n_in,
                              void* d_out, int out_size) {
    const float* x    = (const float*)d_in[0];
    const float* wgt  = (const float*)d_in[1];
    const float* bias = (const float*)d_in[2];
    float* out        = (float*)d_out;

    cudaFuncSetAttribute(conv_mma_fp16_kernel,
                         cudaFuncAttributeMaxDynamicSharedMemorySize, SMEM_TOTAL);

    prep_kernel<<<WPREP_BLOCKS + XPREP_BLOCKS, 256>>>(wgt, x);
    conv_mma_fp16_kernel<<<NCTAS, NTHREADS, SMEM_TOTAL>>>(bias, out);
}